// round 5
// baseline (speedup 1.0000x reference)
#include <cuda_runtime.h>
#include <cstdint>

// ----------------------------------------------------------------------------
// GCNConv: out = (D^-1/2 A D^-1/2)(X W) + bias,  N=8192, DIN=DOUT=256, fp32
//   k_pre (fused, one launch):
//     blocks [0,512):    ZTraw[n,k] = tf32_rne( (X@W)[k,n] )   (no d!)
//     blocks [512,8704): deg row-sums -> g_d = (rowsum+l)^-1/2
//   k_gemm: out[m,n] = d[m] * sum_k (adj[m,k]*d[k]) * ZTraw[n,k] + bias[n]
//     mma.sync.m16n8k8 tf32, BK=32, 3-stage cp.async; d[k] folded into the
//     A fragment (fp32 FMUL before tf32 rne -> same rounding count as before).
// ----------------------------------------------------------------------------

#define N_NODES 8192
#define FDIM    256

__device__ float g_d[N_NODES];
__device__ float g_ZT[FDIM * (size_t)N_NODES];

// ---------------- helpers ---------------------------------------------------
__device__ __forceinline__ uint32_t smem_u32(const void* p) {
    uint32_t a;
    asm("{ .reg .u64 t; cvta.to.shared.u64 t, %1; cvt.u32.u64 %0, t; }"
        : "=r"(a) : "l"(p));
    return a;
}
__device__ __forceinline__ void cp16(uint32_t dst, const void* src) {
    asm volatile("cp.async.cg.shared.global [%0], [%1], 16;"
                 :: "r"(dst), "l"(src) : "memory");
}
__device__ __forceinline__ uint32_t f2tf32(float x) {
    uint32_t r;
    asm("cvt.rna.tf32.f32 %0, %1;" : "=r"(r) : "f"(x));
    return r;
}
__device__ __forceinline__ void mma_16n8k8(float* d, const uint32_t* a,
                                           const uint32_t* b) {
    asm volatile(
        "mma.sync.aligned.m16n8k8.row.col.f32.tf32.tf32.f32 "
        "{%0,%1,%2,%3}, {%4,%5,%6,%7}, {%8,%9}, {%0,%1,%2,%3};"
        : "+f"(d[0]), "+f"(d[1]), "+f"(d[2]), "+f"(d[3])
        : "r"(a[0]), "r"(a[1]), "r"(a[2]), "r"(a[3]), "r"(b[0]), "r"(b[1]));
}

// robust scalar 'l' reader: handles int32/int64 (small) and fp32 encodings
__device__ __forceinline__ float read_l(const void* p) {
    int i = *(const int*)p;
    if (i >= 0 && i < (1 << 24)) return (float)i;
    return __int_as_float(i);
}

// ---------------- k_pre: fused XW (no d) + degree ---------------------------
#define PRE_XW_BLOCKS 512   // XW blocks first so they overlap the deg wave

__global__ __launch_bounds__(256) void k_pre(const float* __restrict__ adj,
                                             const float* __restrict__ X,
                                             const float* __restrict__ W,
                                             const void* __restrict__ lptr) {
    if (blockIdx.x < PRE_XW_BLOCKS) {
        // ---- ZTraw = rne_tf32((X@W)^T), tile 64(k) x 64(n) ----
        __shared__ float Xs[64][17];
        __shared__ float Ws[16][65];
        int k0 = (blockIdx.x >> 2) * 64, n0 = (blockIdx.x & 3) * 64;
        int t = threadIdx.x;
        int tx = t & 15, ty = t >> 4;
        float acc[4][4] = {};
        for (int c0 = 0; c0 < FDIM; c0 += 16) {
#pragma unroll
            for (int e = t; e < 1024; e += 256) {
                int r = e >> 4, c = e & 15;
                Xs[r][c] = X[(size_t)(k0 + r) * FDIM + c0 + c];
            }
#pragma unroll
            for (int e = t; e < 1024; e += 256) {
                int c = e >> 6, n = e & 63;
                Ws[c][n] = W[(size_t)(c0 + c) * FDIM + n0 + n];
            }
            __syncthreads();
#pragma unroll
            for (int c = 0; c < 16; c++) {
                float a0 = Xs[ty * 4 + 0][c], a1 = Xs[ty * 4 + 1][c];
                float a2 = Xs[ty * 4 + 2][c], a3 = Xs[ty * 4 + 3][c];
#pragma unroll
                for (int j = 0; j < 4; j++) {
                    float b = Ws[c][tx * 4 + j];
                    acc[0][j] += a0 * b; acc[1][j] += a1 * b;
                    acc[2][j] += a2 * b; acc[3][j] += a3 * b;
                }
            }
            __syncthreads();
        }
#pragma unroll
        for (int r = 0; r < 4; r++) {
            int k = k0 + ty * 4 + r;
#pragma unroll
            for (int j = 0; j < 4; j++) {
                int n = n0 + tx * 4 + j;
                g_ZT[(size_t)n * N_NODES + k] =
                    __uint_as_float(f2tf32(acc[r][j]));
            }
        }
    } else {
        // ---- degree + D^{-1/2} ----
        int row = blockIdx.x - PRE_XW_BLOCKS;
        const float4* p = (const float4*)(adj + (size_t)row * N_NODES);
        float s = 0.f;
#pragma unroll
        for (int i = 0; i < 8; i++) {
            float4 v = p[threadIdx.x + i * 256];
            s += (v.x + v.y) + (v.z + v.w);
        }
#pragma unroll
        for (int o = 16; o; o >>= 1) s += __shfl_xor_sync(0xffffffffu, s, o);
        __shared__ float ws[8];
        if ((threadIdx.x & 31) == 0) ws[threadIdx.x >> 5] = s;
        __syncthreads();
        if (threadIdx.x == 0) {
            float t = 0.f;
#pragma unroll
            for (int w = 0; w < 8; w++) t += ws[w];
            float deg = t + read_l(lptr);
            g_d[row] = deg > 0.f ? rsqrtf(deg) : 0.f;
        }
    }
}

// ---------------- K3: mma.sync tf32 GEMM (d folded into A frags) ------------
// BM=64, BN=256, BK=32, 3-stage cp.async ring, 128 CTAs (1 wave).
// 8 warps in 2x4 grid; warp tile 32x64 (2x8 m16n8k8 tiles), 4 k-steps/iter.
// Row stride 36 floats: fragment LDS bank = (4r+t)%32 -> conflict-free.
#define BM     64
#define BN     256
#define BK     32
#define NIT    (N_NODES / BK)     // 256
#define STAGES 3
#define ASTR   36
#define A_ST   (BM * ASTR)        // 2304 floats
#define B_ST   (BN * ASTR)        // 9216 floats
#define SMEM_FLOATS (STAGES * (A_ST + B_ST) + FDIM + STAGES * BK)
#define SMEM_BYTES  (SMEM_FLOATS * 4)

__device__ __forceinline__ void issue_stage(const float* __restrict__ adj,
                                            int m0, float* sA, float* sB,
                                            float* sD, int tid, int it, int s) {
    int k0 = it * BK;
#pragma unroll
    for (int j = 0; j < 2; j++) {   // A: 64 rows x 32 floats
        int f = tid + j * 256, r = f >> 3, c4 = (f & 7) * 4;
        cp16(smem_u32(sA + s * A_ST + r * ASTR + c4),
             adj + (size_t)(m0 + r) * N_NODES + k0 + c4);
    }
#pragma unroll
    for (int j = 0; j < 8; j++) {   // B: 256 rows x 32 floats
        int f = tid + j * 256, r = f >> 3, c4 = (f & 7) * 4;
        cp16(smem_u32(sB + s * B_ST + r * ASTR + c4),
             g_ZT + (size_t)r * N_NODES + k0 + c4);
    }
    if (tid < 8)                    // d tile: 32 floats
        cp16(smem_u32(sD + s * BK + tid * 4), g_d + k0 + tid * 4);
}

__global__ __launch_bounds__(256, 1)
void k_gemm(const float* __restrict__ adj, const float* __restrict__ bias,
            float* __restrict__ out) {
    extern __shared__ float sm[];
    float* sA = sm;
    float* sB = sm + STAGES * A_ST;
    float* sBias = sB + STAGES * B_ST;
    float* sD = sBias + FDIM;

    int tid = threadIdx.x, wid = tid >> 5, lane = tid & 31;
    int grp = lane >> 2, tig = lane & 3;
    int warpm = wid >> 2, warpn = wid & 3;   // 2 x 4 warp grid
    int m0 = blockIdx.x * BM;

    if (tid < FDIM) sBias[tid] = bias[tid];

    issue_stage(adj, m0, sA, sB, sD, tid, 0, 0);
    asm volatile("cp.async.commit_group;" ::: "memory");
    issue_stage(adj, m0, sA, sB, sD, tid, 1, 1);
    asm volatile("cp.async.commit_group;" ::: "memory");

    float acc[2][8][4] = {};
    int s_cur = 0, s_nxt = STAGES - 1;

#pragma unroll 1
    for (int it = 0; it < NIT; ++it) {
        asm volatile("cp.async.wait_group %0;" :: "n"(STAGES - 2) : "memory");
        __syncthreads();
        const float* As = sA + s_cur * A_ST;
        const float* Bs = sB + s_cur * B_ST;
        const float* Ds = sD + s_cur * BK;
#pragma unroll
        for (int kk = 0; kk < 4; kk++) {
            int kb = kk * 8 + tig;
            float dk0 = Ds[kb], dk4 = Ds[kb + 4];
            uint32_t a[2][4];
#pragma unroll
            for (int mt = 0; mt < 2; mt++) {
                int r0 = warpm * 32 + mt * 16 + grp;
                a[mt][0] = f2tf32(As[r0 * ASTR + kb] * dk0);
                a[mt][1] = f2tf32(As[(r0 + 8) * ASTR + kb] * dk0);
                a[mt][2] = f2tf32(As[r0 * ASTR + kb + 4] * dk4);
                a[mt][3] = f2tf32(As[(r0 + 8) * ASTR + kb + 4] * dk4);
            }
            uint32_t b[8][2];
#pragma unroll
            for (int nt = 0; nt < 8; nt++) {
                int n = warpn * 64 + nt * 8 + grp;
                b[nt][0] = __float_as_uint(Bs[n * ASTR + kb]);
                b[nt][1] = __float_as_uint(Bs[n * ASTR + kb + 4]);
            }
#pragma unroll
            for (int mt = 0; mt < 2; mt++)
#pragma unroll
                for (int nt = 0; nt < 8; nt++)
                    mma_16n8k8(acc[mt][nt], a[mt], b[nt]);
        }
        if (it + STAGES - 1 < NIT)
            issue_stage(adj, m0, sA, sB, sD, tid, it + STAGES - 1, s_nxt);
        asm volatile("cp.async.commit_group;" ::: "memory");
        if (++s_cur == STAGES) s_cur = 0;
        if (++s_nxt == STAGES) s_nxt = 0;
    }

    // ---- epilogue: out = d[m]*acc + bias ----
#pragma unroll
    for (int mt = 0; mt < 2; mt++) {
        int r0 = m0 + warpm * 32 + mt * 16 + grp;
        float d0 = g_d[r0], d1 = g_d[r0 + 8];
        float* o0 = out + (size_t)r0 * FDIM;
        float* o1 = out + (size_t)(r0 + 8) * FDIM;
#pragma unroll
        for (int nt = 0; nt < 8; nt++) {
            int n = warpn * 64 + nt * 8 + 2 * tig;
            float2 v0, v1;
            v0.x = acc[mt][nt][0] * d0 + sBias[n];
            v0.y = acc[mt][nt][1] * d0 + sBias[n + 1];
            v1.x = acc[mt][nt][2] * d1 + sBias[n];
            v1.y = acc[mt][nt][3] * d1 + sBias[n + 1];
            *(float2*)(o0 + n) = v0;
            *(float2*)(o1 + n) = v1;
        }
    }
}

// ---------------- launch ----------------------------------------------------
extern "C" void kernel_launch(void* const* d_in, const int* in_sizes, int n_in,
                              void* d_out, int out_size) {
    const float* adj  = (const float*)d_in[0];
    const float* X    = (const float*)d_in[1];
    const float* W    = (const float*)d_in[2];
    const float* bias = (const float*)d_in[3];
    const void*  lptr = d_in[4];
    float* out = (float*)d_out;

    cudaFuncSetAttribute(k_gemm, cudaFuncAttributeMaxDynamicSharedMemorySize,
                         SMEM_BYTES);

    k_pre<<<PRE_XW_BLOCKS + N_NODES, 256>>>(adj, X, W, lptr);
    k_gemm<<<N_NODES / BM, 256, SMEM_BYTES>>>(adj, bias, out);
}

// round 6
// speedup vs baseline: 1.0055x; 1.0055x over previous
#include <cuda_runtime.h>
#include <cstdint>

// ----------------------------------------------------------------------------
// GCNConv: out = (D^-1/2 A D^-1/2)(X W) + bias,  N=8192, DIN=DOUT=256, fp32
//   K1: deg = rowsum(adj)+l ; d = deg^-1/2
//   K2: ZT[n,k] = tf32_rne( d[k] * (X@W)[k,n] )     (K-major B operand)
//   K3: out[m,n] = d[m] * sum_k adj[m,k]*ZT[n,k] + bias[n]
//       mma.sync.m16n8k8 tf32, BK=32, 3-stage cp.async, 512 threads
//       (16 warps: 2x8 grid, 32x32 warp tiles) for latency hiding.
// ----------------------------------------------------------------------------

#define N_NODES 8192
#define FDIM    256

__device__ float g_d[N_NODES];
__device__ float g_ZT[FDIM * (size_t)N_NODES];

// ---------------- helpers ---------------------------------------------------
__device__ __forceinline__ uint32_t smem_u32(const void* p) {
    uint32_t a;
    asm("{ .reg .u64 t; cvta.to.shared.u64 t, %1; cvt.u32.u64 %0, t; }"
        : "=r"(a) : "l"(p));
    return a;
}
__device__ __forceinline__ void cp16(uint32_t dst, const void* src) {
    asm volatile("cp.async.cg.shared.global [%0], [%1], 16;"
                 :: "r"(dst), "l"(src) : "memory");
}
__device__ __forceinline__ uint32_t f2tf32(float x) {
    uint32_t r;
    asm("cvt.rna.tf32.f32 %0, %1;" : "=r"(r) : "f"(x));
    return r;
}
__device__ __forceinline__ void mma_16n8k8(float* d, const uint32_t* a,
                                           const uint32_t* b) {
    asm volatile(
        "mma.sync.aligned.m16n8k8.row.col.f32.tf32.tf32.f32 "
        "{%0,%1,%2,%3}, {%4,%5,%6,%7}, {%8,%9}, {%0,%1,%2,%3};"
        : "+f"(d[0]), "+f"(d[1]), "+f"(d[2]), "+f"(d[3])
        : "r"(a[0]), "r"(a[1]), "r"(a[2]), "r"(a[3]), "r"(b[0]), "r"(b[1]));
}

// robust scalar 'l' reader: handles int32/int64 (small) and fp32 encodings
__device__ __forceinline__ float read_l(const void* p) {
    int i = *(const int*)p;
    if (i >= 0 && i < (1 << 24)) return (float)i;
    return __int_as_float(i);
}

// ---------------- K1: degree + D^{-1/2} -------------------------------------
__global__ __launch_bounds__(256) void k_deg(const float* __restrict__ adj,
                                             const void* __restrict__ lptr) {
    int row = blockIdx.x;
    const float4* p = (const float4*)(adj + (size_t)row * N_NODES);
    float s = 0.f;
#pragma unroll
    for (int i = 0; i < 8; i++) {
        float4 v = p[threadIdx.x + i * 256];
        s += (v.x + v.y) + (v.z + v.w);
    }
#pragma unroll
    for (int o = 16; o; o >>= 1) s += __shfl_xor_sync(0xffffffffu, s, o);
    __shared__ float ws[8];
    if ((threadIdx.x & 31) == 0) ws[threadIdx.x >> 5] = s;
    __syncthreads();
    if (threadIdx.x == 0) {
        float t = 0.f;
#pragma unroll
        for (int w = 0; w < 8; w++) t += ws[w];
        float deg = t + read_l(lptr);
        g_d[row] = deg > 0.f ? rsqrtf(deg) : 0.f;
    }
}

// ---------------- K2: ZT = d ∘ (X@W), transposed + tf32-rne -----------------
__global__ __launch_bounds__(256) void k_support(const float* __restrict__ X,
                                                 const float* __restrict__ W) {
    __shared__ float Xs[64][17];
    __shared__ float Ws[16][65];
    int k0 = blockIdx.x * 64, n0 = blockIdx.y * 64;
    int t = threadIdx.x;
    int tx = t & 15, ty = t >> 4;
    float acc[4][4] = {};
    for (int c0 = 0; c0 < FDIM; c0 += 16) {
#pragma unroll
        for (int e = t; e < 1024; e += 256) {
            int r = e >> 4, c = e & 15;
            Xs[r][c] = X[(size_t)(k0 + r) * FDIM + c0 + c];
        }
#pragma unroll
        for (int e = t; e < 1024; e += 256) {
            int c = e >> 6, n = e & 63;
            Ws[c][n] = W[(size_t)(c0 + c) * FDIM + n0 + n];
        }
        __syncthreads();
#pragma unroll
        for (int c = 0; c < 16; c++) {
            float a0 = Xs[ty * 4 + 0][c], a1 = Xs[ty * 4 + 1][c];
            float a2 = Xs[ty * 4 + 2][c], a3 = Xs[ty * 4 + 3][c];
#pragma unroll
            for (int j = 0; j < 4; j++) {
                float b = Ws[c][tx * 4 + j];
                acc[0][j] += a0 * b; acc[1][j] += a1 * b;
                acc[2][j] += a2 * b; acc[3][j] += a3 * b;
            }
        }
        __syncthreads();
    }
#pragma unroll
    for (int r = 0; r < 4; r++) {
        int k = k0 + ty * 4 + r;
        float dk = g_d[k];
#pragma unroll
        for (int j = 0; j < 4; j++) {
            int n = n0 + tx * 4 + j;
            g_ZT[(size_t)n * N_NODES + k] =
                __uint_as_float(f2tf32(dk * acc[r][j]));
        }
    }
}

// ---------------- K3: mma.sync tf32 GEMM (512 thr, 32x32 warp tiles) --------
// BM=64, BN=256, BK=32, 3-stage cp.async ring, 128 CTAs (1 wave).
// 16 warps in 2(m) x 8(n) grid; warp tile 32x32 (2x4 m16n8k8), 4 ksteps/iter.
// Row stride 36 floats: fragment LDS bank = (4*grp+tig)%32 -> conflict-free.
#define BM     64
#define BN     256
#define BK     32
#define NIT    (N_NODES / BK)     // 256
#define STAGES 3
#define ASTR   36
#define A_ST   (BM * ASTR)        // 2304 floats
#define B_ST   (BN * ASTR)        // 9216 floats
#define SMEM_FLOATS (STAGES * (A_ST + B_ST) + FDIM)
#define SMEM_BYTES  (SMEM_FLOATS * 4)   // 139264
#define NTHREADS 512

__device__ __forceinline__ void issue_stage(const float* __restrict__ adj,
                                            int m0, float* sA, float* sB,
                                            int tid, int it, int s) {
    int k0 = it * BK;
    {                               // A: 64 rows x 32 floats (512 float4)
        int r = tid >> 3, c4 = (tid & 7) * 4;
        cp16(smem_u32(sA + s * A_ST + r * ASTR + c4),
             adj + (size_t)(m0 + r) * N_NODES + k0 + c4);
    }
#pragma unroll
    for (int j = 0; j < 4; j++) {   // B: 256 rows x 32 floats (2048 float4)
        int f = tid + j * NTHREADS, r = f >> 3, c4 = (f & 7) * 4;
        cp16(smem_u32(sB + s * B_ST + r * ASTR + c4),
             g_ZT + (size_t)r * N_NODES + k0 + c4);
    }
}

__global__ __launch_bounds__(NTHREADS, 1)
void k_gemm(const float* __restrict__ adj, const float* __restrict__ bias,
            float* __restrict__ out) {
    extern __shared__ float sm[];
    float* sA = sm;
    float* sB = sm + STAGES * A_ST;
    float* sBias = sB + STAGES * B_ST;

    int tid = threadIdx.x, wid = tid >> 5, lane = tid & 31;
    int grp = lane >> 2, tig = lane & 3;
    int warpm = wid >> 3, warpn = wid & 7;   // 2 x 8 warp grid
    int m0 = blockIdx.x * BM;

    if (tid < FDIM) sBias[tid] = bias[tid];

    issue_stage(adj, m0, sA, sB, tid, 0, 0);
    asm volatile("cp.async.commit_group;" ::: "memory");
    issue_stage(adj, m0, sA, sB, tid, 1, 1);
    asm volatile("cp.async.commit_group;" ::: "memory");

    float acc[2][4][4] = {};
    int s_cur = 0, s_nxt = STAGES - 1;

#pragma unroll 1
    for (int it = 0; it < NIT; ++it) {
        asm volatile("cp.async.wait_group %0;" :: "n"(STAGES - 2) : "memory");
        __syncthreads();
        const float* As = sA + s_cur * A_ST;
        const float* Bs = sB + s_cur * B_ST;
#pragma unroll
        for (int kk = 0; kk < 4; kk++) {
            int kb = kk * 8 + tig;
            uint32_t a[2][4];
#pragma unroll
            for (int mt = 0; mt < 2; mt++) {
                int r0 = warpm * 32 + mt * 16 + grp;
                a[mt][0] = f2tf32(As[r0 * ASTR + kb]);
                a[mt][1] = f2tf32(As[(r0 + 8) * ASTR + kb]);
                a[mt][2] = f2tf32(As[r0 * ASTR + kb + 4]);
                a[mt][3] = f2tf32(As[(r0 + 8) * ASTR + kb + 4]);
            }
            uint32_t b[4][2];
#pragma unroll
            for (int nt = 0; nt < 4; nt++) {
                int n = warpn * 32 + nt * 8 + grp;
                b[nt][0] = __float_as_uint(Bs[n * ASTR + kb]);
                b[nt][1] = __float_as_uint(Bs[n * ASTR + kb + 4]);
            }
#pragma unroll
            for (int mt = 0; mt < 2; mt++)
#pragma unroll
                for (int nt = 0; nt < 4; nt++)
                    mma_16n8k8(acc[mt][nt], a[mt], b[nt]);
        }
        if (it + STAGES - 1 < NIT)
            issue_stage(adj, m0, sA, sB, tid, it + STAGES - 1, s_nxt);
        asm volatile("cp.async.commit_group;" ::: "memory");
        if (++s_cur == STAGES) s_cur = 0;
        if (++s_nxt == STAGES) s_nxt = 0;
    }

    // ---- epilogue: out = d[m]*acc + bias ----
#pragma unroll
    for (int mt = 0; mt < 2; mt++) {
        int r0 = m0 + warpm * 32 + mt * 16 + grp;
        float d0 = g_d[r0], d1 = g_d[r0 + 8];
        float* o0 = out + (size_t)r0 * FDIM;
        float* o1 = out + (size_t)(r0 + 8) * FDIM;
#pragma unroll
        for (int nt = 0; nt < 4; nt++) {
            int n = warpn * 32 + nt * 8 + 2 * tig;
            float2 v0, v1;
            v0.x = acc[mt][nt][0] * d0 + sBias[n];
            v0.y = acc[mt][nt][1] * d0 + sBias[n + 1];
            v1.x = acc[mt][nt][2] * d1 + sBias[n];
            v1.y = acc[mt][nt][3] * d1 + sBias[n + 1];
            *(float2*)(o0 + n) = v0;
            *(float2*)(o1 + n) = v1;
        }
    }
}

// ---------------- launch ----------------------------------------------------
extern "C" void kernel_launch(void* const* d_in, const int* in_sizes, int n_in,
                              void* d_out, int out_size) {
    const float* adj  = (const float*)d_in[0];
    const float* X    = (const float*)d_in[1];
    const float* W    = (const float*)d_in[2];
    const float* bias = (const float*)d_in[3];
    const void*  lptr = d_in[4];
    float* out = (float*)d_out;

    cudaFuncSetAttribute(k_gemm, cudaFuncAttributeMaxDynamicSharedMemorySize,
                         SMEM_BYTES);

    k_deg<<<N_NODES, 256>>>(adj, lptr);
    k_support<<<dim3(N_NODES / 64, FDIM / 64), 256>>>(X, W);
    k_gemm<<<N_NODES / BM, NTHREADS, SMEM_BYTES>>>(adj, bias, out);
}

// round 7
// speedup vs baseline: 1.0290x; 1.0233x over previous
#include <cuda_runtime.h>
#include <cstdint>

// ----------------------------------------------------------------------------
// GCNConv: out = (D^-1/2 A D^-1/2)(X W) + bias,  N=8192, DIN=DOUT=256, fp32
//   K1: deg = rowsum(adj)+l ; d = deg^-1/2
//   K2: ZT[n,k] = tf32_rne( d[k] * (X@W)[k,n] )     (K-major B operand)
//   K3: out[m,n] = d[m] * sum_k adj[m,k]*ZT[n,k] + bias[n]
//       mma.sync.m16n8k8 tf32, BK=32, 4-stage cp.async ring,
//       software-pipelined fragment loads (k-step k+1 LDS hidden behind
//       k-step k HMMAs).
// ----------------------------------------------------------------------------

#define N_NODES 8192
#define FDIM    256

__device__ float g_d[N_NODES];
__device__ float g_ZT[FDIM * (size_t)N_NODES];

// ---------------- helpers ---------------------------------------------------
__device__ __forceinline__ uint32_t smem_u32(const void* p) {
    uint32_t a;
    asm("{ .reg .u64 t; cvta.to.shared.u64 t, %1; cvt.u32.u64 %0, t; }"
        : "=r"(a) : "l"(p));
    return a;
}
__device__ __forceinline__ void cp16(uint32_t dst, const void* src) {
    asm volatile("cp.async.cg.shared.global [%0], [%1], 16;"
                 :: "r"(dst), "l"(src) : "memory");
}
__device__ __forceinline__ uint32_t f2tf32(float x) {
    uint32_t r;
    asm("cvt.rna.tf32.f32 %0, %1;" : "=r"(r) : "f"(x));
    return r;
}
__device__ __forceinline__ void mma_16n8k8(float* d, const uint32_t* a,
                                           const uint32_t* b) {
    asm volatile(
        "mma.sync.aligned.m16n8k8.row.col.f32.tf32.tf32.f32 "
        "{%0,%1,%2,%3}, {%4,%5,%6,%7}, {%8,%9}, {%0,%1,%2,%3};"
        : "+f"(d[0]), "+f"(d[1]), "+f"(d[2]), "+f"(d[3])
        : "r"(a[0]), "r"(a[1]), "r"(a[2]), "r"(a[3]), "r"(b[0]), "r"(b[1]));
}

// robust scalar 'l' reader: handles int32/int64 (small) and fp32 encodings
__device__ __forceinline__ float read_l(const void* p) {
    int i = *(const int*)p;
    if (i >= 0 && i < (1 << 24)) return (float)i;
    return __int_as_float(i);
}

// ---------------- K1: degree + D^{-1/2} -------------------------------------
__global__ __launch_bounds__(256) void k_deg(const float* __restrict__ adj,
                                             const void* __restrict__ lptr) {
    int row = blockIdx.x;
    const float4* p = (const float4*)(adj + (size_t)row * N_NODES);
    float s = 0.f;
#pragma unroll
    for (int i = 0; i < 8; i++) {
        float4 v = p[threadIdx.x + i * 256];
        s += (v.x + v.y) + (v.z + v.w);
    }
#pragma unroll
    for (int o = 16; o; o >>= 1) s += __shfl_xor_sync(0xffffffffu, s, o);
    __shared__ float ws[8];
    if ((threadIdx.x & 31) == 0) ws[threadIdx.x >> 5] = s;
    __syncthreads();
    if (threadIdx.x == 0) {
        float t = 0.f;
#pragma unroll
        for (int w = 0; w < 8; w++) t += ws[w];
        float deg = t + read_l(lptr);
        g_d[row] = deg > 0.f ? rsqrtf(deg) : 0.f;
    }
}

// ---------------- K2: ZT = d ∘ (X@W), transposed + tf32-rne -----------------
__global__ __launch_bounds__(256) void k_support(const float* __restrict__ X,
                                                 const float* __restrict__ W) {
    __shared__ float Xs[64][17];
    __shared__ float Ws[16][65];
    int k0 = blockIdx.x * 64, n0 = blockIdx.y * 64;
    int t = threadIdx.x;
    int tx = t & 15, ty = t >> 4;
    float acc[4][4] = {};
    for (int c0 = 0; c0 < FDIM; c0 += 16) {
#pragma unroll
        for (int e = t; e < 1024; e += 256) {
            int r = e >> 4, c = e & 15;
            Xs[r][c] = X[(size_t)(k0 + r) * FDIM + c0 + c];
        }
#pragma unroll
        for (int e = t; e < 1024; e += 256) {
            int c = e >> 6, n = e & 63;
            Ws[c][n] = W[(size_t)(c0 + c) * FDIM + n0 + n];
        }
        __syncthreads();
#pragma unroll
        for (int c = 0; c < 16; c++) {
            float a0 = Xs[ty * 4 + 0][c], a1 = Xs[ty * 4 + 1][c];
            float a2 = Xs[ty * 4 + 2][c], a3 = Xs[ty * 4 + 3][c];
#pragma unroll
            for (int j = 0; j < 4; j++) {
                float b = Ws[c][tx * 4 + j];
                acc[0][j] += a0 * b; acc[1][j] += a1 * b;
                acc[2][j] += a2 * b; acc[3][j] += a3 * b;
            }
        }
        __syncthreads();
    }
#pragma unroll
    for (int r = 0; r < 4; r++) {
        int k = k0 + ty * 4 + r;
        float dk = g_d[k];
#pragma unroll
        for (int j = 0; j < 4; j++) {
            int n = n0 + tx * 4 + j;
            g_ZT[(size_t)n * N_NODES + k] =
                __uint_as_float(f2tf32(dk * acc[r][j]));
        }
    }
}

// ---------------- K3: mma.sync tf32 GEMM (4 stages, pipelined frags) --------
// BM=64, BN=256, BK=32, 4-stage cp.async ring, 128 CTAs (1 wave).
// 8 warps in 2x4 grid; warp tile 32x64 (2x8 m16n8k8 tiles), 4 k-steps/iter.
// Row stride 36 floats: fragment LDS bank = (4*grp+tig)%32 -> conflict-free.
#define BM     64
#define BN     256
#define BK     32
#define NIT    (N_NODES / BK)     // 256
#define STAGES 4
#define ASTR   36
#define A_ST   (BM * ASTR)        // 2304 floats
#define B_ST   (BN * ASTR)        // 9216 floats
#define SMEM_FLOATS (STAGES * (A_ST + B_ST) + FDIM)
#define SMEM_BYTES  (SMEM_FLOATS * 4)   // 185344

__device__ __forceinline__ void issue_stage(const float* __restrict__ adj,
                                            int m0, float* sA, float* sB,
                                            int tid, int it, int s) {
    int k0 = it * BK;
#pragma unroll
    for (int j = 0; j < 2; j++) {   // A: 64 rows x 32 floats
        int f = tid + j * 256, r = f >> 3, c4 = (f & 7) * 4;
        cp16(smem_u32(sA + s * A_ST + r * ASTR + c4),
             adj + (size_t)(m0 + r) * N_NODES + k0 + c4);
    }
#pragma unroll
    for (int j = 0; j < 8; j++) {   // B: 256 rows x 32 floats
        int f = tid + j * 256, r = f >> 3, c4 = (f & 7) * 4;
        cp16(smem_u32(sB + s * B_ST + r * ASTR + c4),
             g_ZT + (size_t)r * N_NODES + k0 + c4);
    }
}

__global__ __launch_bounds__(256, 1)
void k_gemm(const float* __restrict__ adj, const float* __restrict__ bias,
            float* __restrict__ out) {
    extern __shared__ float sm[];
    float* sA = sm;
    float* sB = sm + STAGES * A_ST;
    float* sBias = sB + STAGES * B_ST;

    int tid = threadIdx.x, wid = tid >> 5, lane = tid & 31;
    int grp = lane >> 2, tig = lane & 3;
    int warpm = wid >> 2, warpn = wid & 3;   // 2 x 4 warp grid
    int m0 = blockIdx.x * BM;

    if (tid < FDIM) sBias[tid] = bias[tid];

    issue_stage(adj, m0, sA, sB, tid, 0, 0);
    asm volatile("cp.async.commit_group;" ::: "memory");
    issue_stage(adj, m0, sA, sB, tid, 1, 1);
    asm volatile("cp.async.commit_group;" ::: "memory");
    issue_stage(adj, m0, sA, sB, tid, 2, 2);
    asm volatile("cp.async.commit_group;" ::: "memory");

    float acc[2][8][4] = {};
    int s_cur = 0, s_nxt = STAGES - 1;

    // fragment row bases (constant across iterations)
    int ar0 = warpm * 32 + grp;            // A rows: ar0, ar0+8 (+16 for mt=1)
    int bn0 = warpn * 64 + grp;            // B rows: bn0 + nt*8

#pragma unroll 1
    for (int it = 0; it < NIT; ++it) {
        asm volatile("cp.async.wait_group %0;" :: "n"(STAGES - 2) : "memory");
        __syncthreads();
        const float* As = sA + s_cur * A_ST;
        const float* Bs = sB + s_cur * B_ST;

        uint32_t a[2][2][4];   // [buf][mt][reg]
        uint32_t b[2][8][2];   // [buf][nt][reg]

        // preload k-step 0 fragments
        {
            int kb = tig;
#pragma unroll
            for (int mt = 0; mt < 2; mt++) {
                int r0 = ar0 + mt * 16;
                a[0][mt][0] = f2tf32(As[r0 * ASTR + kb]);
                a[0][mt][1] = f2tf32(As[(r0 + 8) * ASTR + kb]);
                a[0][mt][2] = f2tf32(As[r0 * ASTR + kb + 4]);
                a[0][mt][3] = f2tf32(As[(r0 + 8) * ASTR + kb + 4]);
            }
#pragma unroll
            for (int nt = 0; nt < 8; nt++) {
                int n = bn0 + nt * 8;
                b[0][nt][0] = __float_as_uint(Bs[n * ASTR + kb]);
                b[0][nt][1] = __float_as_uint(Bs[n * ASTR + kb + 4]);
            }
        }

#pragma unroll
        for (int kk = 0; kk < 4; kk++) {
            int cur = kk & 1, nxt = cur ^ 1;
            if (kk < 3) {   // prefetch next k-step fragments BEFORE the MMAs
                int kb = (kk + 1) * 8 + tig;
#pragma unroll
                for (int mt = 0; mt < 2; mt++) {
                    int r0 = ar0 + mt * 16;
                    a[nxt][mt][0] = f2tf32(As[r0 * ASTR + kb]);
                    a[nxt][mt][1] = f2tf32(As[(r0 + 8) * ASTR + kb]);
                    a[nxt][mt][2] = f2tf32(As[r0 * ASTR + kb + 4]);
                    a[nxt][mt][3] = f2tf32(As[(r0 + 8) * ASTR + kb + 4]);
                }
#pragma unroll
                for (int nt = 0; nt < 8; nt++) {
                    int n = bn0 + nt * 8;
                    b[nxt][nt][0] = __float_as_uint(Bs[n * ASTR + kb]);
                    b[nxt][nt][1] = __float_as_uint(Bs[n * ASTR + kb + 4]);
                }
            }
#pragma unroll
            for (int mt = 0; mt < 2; mt++)
#pragma unroll
                for (int nt = 0; nt < 8; nt++)
                    mma_16n8k8(acc[mt][nt], a[cur][mt], b[cur][nt]);
        }

        if (it + STAGES - 1 < NIT)
            issue_stage(adj, m0, sA, sB, tid, it + STAGES - 1, s_nxt);
        asm volatile("cp.async.commit_group;" ::: "memory");
        if (++s_cur == STAGES) s_cur = 0;
        if (++s_nxt == STAGES) s_nxt = 0;
    }

    // ---- epilogue: out = d[m]*acc + bias ----
#pragma unroll
    for (int mt = 0; mt < 2; mt++) {
        int r0 = m0 + warpm * 32 + mt * 16 + grp;
        float d0 = g_d[r0], d1 = g_d[r0 + 8];
        float* o0 = out + (size_t)r0 * FDIM;
        float* o1 = out + (size_t)(r0 + 8) * FDIM;
#pragma unroll
        for (int nt = 0; nt < 8; nt++) {
            int n = warpn * 64 + nt * 8 + 2 * tig;
            float2 v0, v1;
            v0.x = acc[mt][nt][0] * d0 + sBias[n];
            v0.y = acc[mt][nt][1] * d0 + sBias[n + 1];
            v1.x = acc[mt][nt][2] * d1 + sBias[n];
            v1.y = acc[mt][nt][3] * d1 + sBias[n + 1];
            *(float2*)(o0 + n) = v0;
            *(float2*)(o1 + n) = v1;
        }
    }
}

// ---------------- launch ----------------------------------------------------
extern "C" void kernel_launch(void* const* d_in, const int* in_sizes, int n_in,
                              void* d_out, int out_size) {
    const float* adj  = (const float*)d_in[0];
    const float* X    = (const float*)d_in[1];
    const float* W    = (const float*)d_in[2];
    const float* bias = (const float*)d_in[3];
    const void*  lptr = d_in[4];
    float* out = (float*)d_out;

    cudaFuncSetAttribute(k_gemm, cudaFuncAttributeMaxDynamicSharedMemorySize,
                         SMEM_BYTES);

    k_deg<<<N_NODES, 256>>>(adj, lptr);
    k_support<<<dim3(N_NODES / 64, FDIM / 64), 256>>>(X, W);
    k_gemm<<<N_NODES / BM, 256, SMEM_BYTES>>>(adj, bias, out);
}